// round 16
// baseline (speedup 1.0000x reference)
#include <cuda_runtime.h>

#define MAXN 400000
#define MAXPAIR (MAXN * 26)
#define BN_EPS 1e-4f
#define FULLM 0xffffffffu

// ---------------- scratch (device globals; no allocations allowed) ----------
__device__ float g_xv  [(size_t)MAXN * 32];
__device__ float g_e0  [(size_t)MAXN * 32];
__device__ float g_down[(size_t)MAXN * 64];
__device__ float g_e1  [(size_t)MAXN * 64];
__device__ float g_up  [(size_t)MAXN * 32];
__device__ float g_dec [(size_t)MAXN * 32];
__device__ float g_bn[3 * 128];            // per-bn: [0:64) sums, [64:128) sumsq

__device__ int2          g_pf [MAXPAIR];   // fine pairs (dst, src)
__device__ unsigned char g_pfk[MAXPAIR];
__device__ int2          g_pc [MAXPAIR];   // coarse pairs
__device__ unsigned char g_pck[MAXPAIR];
__device__ int g_np[2];                    // pair-list cursors / totals

// packed weights: (ci-pair) x cout layout so LDS.128 feature reads feed FFMA2
__device__ float2 g_wp0[27 * 16 * 32];
__device__ float4 g_wp1q[27 * 32 * 32];
__device__ float2 g_wpd[27 * 32 * 32];

// ---------------- f32x2 helpers ---------------------------------------------
__device__ __forceinline__ unsigned long long pk2(float x, float y) {
    unsigned long long r;
    asm("mov.b64 %0, {%1, %2};" : "=l"(r) : "f"(x), "f"(y));
    return r;
}
__device__ __forceinline__ unsigned long long fma2(unsigned long long a,
                                                   unsigned long long b,
                                                   unsigned long long c) {
    unsigned long long d;
    asm("fma.rn.f32x2 %0, %1, %2, %3;" : "=l"(d) : "l"(a), "l"(b), "l"(c));
    return d;
}
__device__ __forceinline__ void unpk2(unsigned long long a, float& x, float& y) {
    asm("mov.b64 {%0, %1}, %2;" : "=f"(x), "=f"(y) : "l"(a));
}
__device__ __forceinline__ unsigned long long add2(unsigned long long a,
                                                   unsigned long long b) {
    unsigned long long d;
    asm("add.rn.f32x2 %0, %1, %2;" : "=l"(d) : "l"(a), "l"(b));
    return d;
}
__device__ __forceinline__ void red2(float* p, float x, float y) {
    asm volatile("red.global.add.v2.f32 [%0], {%1, %2};" :: "l"(p), "f"(x), "f"(y));
}

// ---------------- weight packing (once per launch, ~775KB) ------------------
__global__ void pack_weights(const float* __restrict__ W0, const float* __restrict__ W1,
                             const float* __restrict__ Wd) {
    int t = blockIdx.x * blockDim.x + threadIdx.x;
    if (t < 27 * 16 * 32) {
        int k = t / 512, r = t % 512, cp = r / 32, co = r % 32;
        g_wp0[t] = make_float2(W0[(k * 32 + 2 * cp) * 32 + co],
                               W0[(k * 32 + 2 * cp + 1) * 32 + co]);
    }
    if (t < 27 * 32 * 32) {
        int k = t / 1024, r = t % 1024, cp = r / 32, cq = r % 32;
        const float* b0 = W1 + (long)(k * 64 + 2 * cp) * 64;
        const float* b1 = W1 + (long)(k * 64 + 2 * cp + 1) * 64;
        g_wp1q[t] = make_float4(b0[2 * cq], b1[2 * cq], b0[2 * cq + 1], b1[2 * cq + 1]);
        g_wpd[t] = make_float2(Wd[(k * 64 + 2 * cp) * 32 + cq],
                               Wd[(k * 64 + 2 * cp + 1) * 32 + cq]);
    }
}

// ---------------- zero: g_down rows, bn accumulators, cursors ---------------
__global__ void zero_kernel(int m) {
    int tid = blockIdx.x * blockDim.x + threadIdx.x;
    int stride = gridDim.x * blockDim.x;
    float4* d4 = (float4*)g_down;
    int n4 = m * 16;
    for (int i = tid; i < n4; i += stride) d4[i] = make_float4(0.f, 0.f, 0.f, 0.f);
    if (blockIdx.x == 0 && threadIdx.x < 128) {
        g_bn[threadIdx.x] = 0.f; g_bn[128 + threadIdx.x] = 0.f; g_bn[256 + threadIdx.x] = 0.f;
        if (threadIdx.x < 2) g_np[threadIdx.x] = 0;
    }
}

// ---------------- single-pass pair building ---------------------------------
#define FILL_VPB 256
__global__ void fill_kernel(const int* __restrict__ nbrF, int nF, int tilesF,
                            const int* __restrict__ nbrC, int nC) {
    int lvl, t0, nv;
    const int* nbr;
    int2* pairs; unsigned char* pkk;
    if ((int)blockIdx.x < tilesF) {
        lvl = 0; t0 = blockIdx.x * FILL_VPB; nbr = nbrF; nv = nF; pairs = g_pf; pkk = g_pfk;
    } else {
        lvl = 1; t0 = (blockIdx.x - tilesF) * FILL_VPB; nbr = nbrC; nv = nC; pairs = g_pc; pkk = g_pck;
    }
    int v = t0 + threadIdx.x;
    __shared__ int cnt[27], cur[27];
    __shared__ int sbase;
    if (threadIdx.x < 27) cnt[threadIdx.x] = 0;
    __syncthreads();
    if (v < nv) {
        const int* row = nbr + (long)v * 27;
        #pragma unroll
        for (int k = 0; k < 27; k++) {
            if (k == 13) continue;
            if (row[k] >= 0) atomicAdd(&cnt[k], 1);
        }
    }
    __syncthreads();
    if (threadIdx.x < 32) {
        int k = threadIdx.x;
        int c = (k < 27) ? cnt[k] : 0;
        int s = c;
        #pragma unroll
        for (int d = 1; d < 32; d <<= 1) {
            int t = __shfl_up_sync(FULLM, s, d);
            if (k >= d) s += t;
        }
        if (k == 26) sbase = atomicAdd(&g_np[lvl], s);
        if (k < 27) cur[k] = s - c;
    }
    __syncthreads();
    if (threadIdx.x < 27) cur[threadIdx.x] += sbase;
    __syncthreads();
    if (v < nv) {
        const int* row = nbr + (long)v * 27;
        #pragma unroll
        for (int k = 0; k < 27; k++) {
            if (k == 13) continue;
            int idx = row[k];
            if (idx >= 0) {
                int pos = atomicAdd(&cur[k], 1);
                pairs[pos] = make_int2(v, idx);
                pkk[pos] = (unsigned char)k;
            }
        }
    }
}

// ---------------- conv 3->32 -------------------------------------------------
__global__ void conv3_center(const float* __restrict__ in, const float* __restrict__ W,
                             float* __restrict__ out, int n) {
    int gw = (blockIdx.x * blockDim.x + threadIdx.x) >> 5;
    int lane = threadIdx.x & 31;
    int nw = (gridDim.x * blockDim.x) >> 5;
    float w0 = __ldg(&W[(13 * 3 + 0) * 32 + lane]);
    float w1 = __ldg(&W[(13 * 3 + 1) * 32 + lane]);
    float w2 = __ldg(&W[(13 * 3 + 2) * 32 + lane]);
    for (int v = gw; v < n; v += nw) {
        float f = (lane < 3) ? __ldg(&in[(long)v * 3 + lane]) : 0.f;
        float a = __shfl_sync(FULLM, f, 0) * w0;
        a = fmaf(__shfl_sync(FULLM, f, 1), w1, a);
        a = fmaf(__shfl_sync(FULLM, f, 2), w2, a);
        out[(long)v * 32 + lane] = a;
    }
}

__global__ void conv3_pair(const float* __restrict__ in, const float* __restrict__ W,
                           float* __restrict__ out, const int2* __restrict__ pairs,
                           const unsigned char* __restrict__ pk, const int* __restrict__ npp) {
    int gw = (blockIdx.x * blockDim.x + threadIdx.x) >> 5;
    int lane = threadIdx.x & 31;
    int nw = (gridDim.x * blockDim.x) >> 5;
    int np = *npp;
    float w0 = 0.f, w1 = 0.f, w2 = 0.f;
    int kcur = -1;
    const int PPW = 32;
    for (int base = gw * PPW; base < np; base += nw * PPW) {
        int cnt = min(PPW, np - base);
        int2 pr = pairs[base];
        int k = pk[base];
        float f = (lane < 3) ? __ldg(&in[(long)pr.y * 3 + lane]) : 0.f;
        for (int m = 0; m < cnt; m++) {
            int2 prn = make_int2(0, 0); int kn = 0; float fn = 0.f;
            if (m + 1 < cnt) {
                prn = pairs[base + m + 1];
                kn = pk[base + m + 1];
                fn = (lane < 3) ? __ldg(&in[(long)prn.y * 3 + lane]) : 0.f;
            }
            if (k != kcur) {
                kcur = k;
                w0 = __ldg(&W[(k * 3 + 0) * 32 + lane]);
                w1 = __ldg(&W[(k * 3 + 1) * 32 + lane]);
                w2 = __ldg(&W[(k * 3 + 2) * 32 + lane]);
            }
            float a = __shfl_sync(FULLM, f, 0) * w0;
            a = fmaf(__shfl_sync(FULLM, f, 1), w1, a);
            a = fmaf(__shfl_sync(FULLM, f, 2), w2, a);
            atomicAdd(&out[(long)pr.x * 32 + lane], a);
            pr = prn; k = kn; f = fn;
        }
    }
}

// ---------------- conv 32->32 ------------------------------------------------
__global__ void conv32_center(const float* __restrict__ in, const float* __restrict__ W,
                              float* __restrict__ out, int n) {
    int gw = (blockIdx.x * blockDim.x + threadIdx.x) >> 5;
    int lane = threadIdx.x & 31;
    int nw = (gridDim.x * blockDim.x) >> 5;
    float w[32];
    #pragma unroll
    for (int ci = 0; ci < 32; ci++) w[ci] = __ldg(&W[(13 * 32 + ci) * 32 + lane]);
    for (int v = gw; v < n; v += nw) {
        float f = __ldg(&in[(long)v * 32 + lane]);
        float a0 = 0.f, a1 = 0.f, a2 = 0.f, a3 = 0.f;
        #pragma unroll
        for (int c = 0; c < 8; c++) {
            a0 = fmaf(__shfl_sync(FULLM, f, 4 * c + 0), w[4 * c + 0], a0);
            a1 = fmaf(__shfl_sync(FULLM, f, 4 * c + 1), w[4 * c + 1], a1);
            a2 = fmaf(__shfl_sync(FULLM, f, 4 * c + 2), w[4 * c + 2], a2);
            a3 = fmaf(__shfl_sync(FULLM, f, 4 * c + 3), w[4 * c + 3], a3);
        }
        out[(long)v * 32 + lane] = (a0 + a1) + (a2 + a3);
    }
}

// pair: smem-staged broadcast, packed (2ci x 1cout) weights, no shfl
__global__ void conv32_pair(const float* __restrict__ in, float* __restrict__ out,
                            const int2* __restrict__ pairs,
                            const unsigned char* __restrict__ pk, const int* __restrict__ npp) {
    __shared__ __align__(16) float sx[8][2][32];
    int wid = threadIdx.x >> 5;
    int lane = threadIdx.x & 31;
    int gw = (blockIdx.x * blockDim.x + threadIdx.x) >> 5;
    int nw = (gridDim.x * blockDim.x) >> 5;
    int np = *npp;
    unsigned long long w[16];
    int kcur = -1;
    const int PPW = 32;
    for (int base = gw * PPW; base < np; base += nw * PPW) {
        int cnt = min(PPW, np - base);
        int2 pr = pairs[base];
        int k = pk[base];
        float f = __ldg(&in[(long)pr.y * 32 + lane]);
        for (int m = 0; m < cnt; m++) {
            int2 prn = make_int2(0, 0); int kn = 0; float fn = 0.f;
            if (m + 1 < cnt) {
                prn = pairs[base + m + 1];
                kn = pk[base + m + 1];
                fn = __ldg(&in[(long)prn.y * 32 + lane]);
            }
            if (k != kcur) {
                kcur = k;
                #pragma unroll
                for (int cp = 0; cp < 16; cp++) {
                    float2 wv = __ldg(&g_wp0[(k * 16 + cp) * 32 + lane]);
                    w[cp] = pk2(wv.x, wv.y);
                }
            }
            int buf = m & 1;
            sx[wid][buf][lane] = f;
            __syncwarp();
            const float4* xs = (const float4*)sx[wid][buf];
            unsigned long long c0 = pk2(0.f, 0.f), c1 = pk2(0.f, 0.f);
            #pragma unroll
            for (int c = 0; c < 8; c++) {
                float4 x = xs[c];
                c0 = fma2(pk2(x.x, x.y), w[2 * c], c0);
                c1 = fma2(pk2(x.z, x.w), w[2 * c + 1], c1);
            }
            float lo, hi; unpk2(add2(c0, c1), lo, hi);
            atomicAdd(&out[(long)pr.x * 32 + lane], lo + hi);
            pr = prn; k = kn; f = fn;
        }
    }
}

// ---------------- conv 64->64 (coarse) ---------------------------------------
__global__ void __launch_bounds__(128)
conv64_center(const float* __restrict__ in, const float* __restrict__ W,
              float* __restrict__ out, int n) {
    int gw = (blockIdx.x * blockDim.x + threadIdx.x) >> 5;
    int lane = threadIdx.x & 31;
    int nw = (gridDim.x * blockDim.x) >> 5;
    unsigned long long w2[64];
    #pragma unroll
    for (int ci = 0; ci < 64; ci++) {
        float2 wv = *(const float2*)(W + (long)(13 * 64 + ci) * 64 + 2 * lane);
        w2[ci] = pk2(wv.x, wv.y);
    }
    for (int v = gw; v < n; v += nw) {
        float2 fv = *(const float2*)(in + (long)v * 64 + 2 * lane);
        unsigned long long a0 = pk2(0.f, 0.f), a1 = pk2(0.f, 0.f);
        unsigned long long a2 = pk2(0.f, 0.f), a3 = pk2(0.f, 0.f);
        #pragma unroll
        for (int j = 0; j < 16; j++) {
            float va0 = __shfl_sync(FULLM, fv.x, 2 * j);
            float vb0 = __shfl_sync(FULLM, fv.y, 2 * j);
            float va1 = __shfl_sync(FULLM, fv.x, 2 * j + 1);
            float vb1 = __shfl_sync(FULLM, fv.y, 2 * j + 1);
            a0 = fma2(pk2(va0, va0), w2[4 * j + 0], a0);
            a1 = fma2(pk2(vb0, vb0), w2[4 * j + 1], a1);
            a2 = fma2(pk2(va1, va1), w2[4 * j + 2], a2);
            a3 = fma2(pk2(vb1, vb1), w2[4 * j + 3], a3);
        }
        float r0, r1; unpk2(add2(add2(a0, a1), add2(a2, a3)), r0, r1);
        *(float2*)(out + (long)v * 64 + 2 * lane) = make_float2(r0, r1);
    }
}

// pair: smem-staged LDS.128 broadcast + packed weights; lane owns couts {2l,2l+1}
// PPW=64: halves k-transition weight reloads and window-boundary overhead
__global__ void __launch_bounds__(128)
conv64_pair(const float* __restrict__ in, float* __restrict__ out,
            const int2* __restrict__ pairs,
            const unsigned char* __restrict__ pk, const int* __restrict__ npp) {
    __shared__ __align__(16) float sx[4][2][64];
    int wid = threadIdx.x >> 5;
    int lane = threadIdx.x & 31;
    int gw = (blockIdx.x * blockDim.x + threadIdx.x) >> 5;
    int nw = (gridDim.x * blockDim.x) >> 5;
    int np = *npp;
    unsigned long long wa[32], wb[32];
    int kcur = -1;
    const int PPW = 64;
    for (int base = gw * PPW; base < np; base += nw * PPW) {
        int cnt = min(PPW, np - base);
        int2 pr = pairs[base];
        int k = pk[base];
        float2 fv = *(const float2*)(in + (long)pr.y * 64 + 2 * lane);
        for (int m = 0; m < cnt; m++) {
            int2 prn = make_int2(0, 0); int kn = 0; float2 fvn = make_float2(0.f, 0.f);
            if (m + 1 < cnt) {
                prn = pairs[base + m + 1];
                kn = pk[base + m + 1];
                fvn = *(const float2*)(in + (long)prn.y * 64 + 2 * lane);
            }
            if (k != kcur) {
                kcur = k;
                #pragma unroll
                for (int cp = 0; cp < 32; cp++) {
                    float4 wv = __ldg(&g_wp1q[(k * 32 + cp) * 32 + lane]);
                    wa[cp] = pk2(wv.x, wv.y);   // cout 2l, ci {2cp, 2cp+1}
                    wb[cp] = pk2(wv.z, wv.w);   // cout 2l+1
                }
            }
            int buf = m & 1;
            *(float2*)&sx[wid][buf][2 * lane] = fv;
            __syncwarp();
            const float4* xs = (const float4*)sx[wid][buf];
            unsigned long long a0 = pk2(0.f, 0.f), a1 = pk2(0.f, 0.f);
            unsigned long long b0 = pk2(0.f, 0.f), b1 = pk2(0.f, 0.f);
            #pragma unroll
            for (int c = 0; c < 16; c++) {
                float4 x = xs[c];
                unsigned long long xp0 = pk2(x.x, x.y);
                unsigned long long xp1 = pk2(x.z, x.w);
                a0 = fma2(xp0, wa[2 * c], a0);
                b0 = fma2(xp0, wb[2 * c], b0);
                a1 = fma2(xp1, wa[2 * c + 1], a1);
                b1 = fma2(xp1, wb[2 * c + 1], b1);
            }
            float al, ah, bl, bh;
            unpk2(add2(a0, a1), al, ah);
            unpk2(add2(b0, b1), bl, bh);
            red2(out + (long)pr.x * 64 + 2 * lane, al + ah, bl + bh);
            pr = prn; k = kn; fv = fvn;
        }
    }
}

// ---------------- conv concat(bnrelu(e0) + up)->32 (decoder) -----------------
__global__ void convcat_center(const float* __restrict__ fA, const float* __restrict__ fB,
                               const float* __restrict__ W,
                               const float* __restrict__ g0, const float* __restrict__ b0,
                               float* __restrict__ out, int n, float inv_n) {
    int gw = (blockIdx.x * blockDim.x + threadIdx.x) >> 5;
    int lane = threadIdx.x & 31;
    int nw = (gridDim.x * blockDim.x) >> 5;
    float mu = g_bn[lane] * inv_n;
    float var = g_bn[64 + lane] * inv_n - mu * mu;
    float rs = rsqrtf(var + BN_EPS) * __ldg(&g0[lane]);
    float bb = __ldg(&b0[lane]);
    float w[64];
    #pragma unroll
    for (int ci = 0; ci < 64; ci++) w[ci] = __ldg(&W[(13 * 64 + ci) * 32 + lane]);
    for (int v = gw; v < n; v += nw) {
        float fa = (__ldg(&fA[(long)v * 32 + lane]) - mu) * rs + bb;
        fa = fa > 0.f ? fa : 0.f;
        float fb = __ldg(&fB[(long)v * 32 + lane]);
        float a0 = 0.f, a1 = 0.f, a2 = 0.f, a3 = 0.f;
        #pragma unroll
        for (int c = 0; c < 8; c++) {
            a0 = fmaf(__shfl_sync(FULLM, fa, 4 * c + 0), w[4 * c + 0], a0);
            a1 = fmaf(__shfl_sync(FULLM, fa, 4 * c + 1), w[4 * c + 1], a1);
            a2 = fmaf(__shfl_sync(FULLM, fa, 4 * c + 2), w[4 * c + 2], a2);
            a3 = fmaf(__shfl_sync(FULLM, fa, 4 * c + 3), w[4 * c + 3], a3);
        }
        #pragma unroll
        for (int c = 0; c < 8; c++) {
            a0 = fmaf(__shfl_sync(FULLM, fb, 4 * c + 0), w[32 + 4 * c + 0], a0);
            a1 = fmaf(__shfl_sync(FULLM, fb, 4 * c + 1), w[32 + 4 * c + 1], a1);
            a2 = fmaf(__shfl_sync(FULLM, fb, 4 * c + 2), w[32 + 4 * c + 2], a2);
            a3 = fmaf(__shfl_sync(FULLM, fb, 4 * c + 3), w[32 + 4 * c + 3], a3);
        }
        out[(long)v * 32 + lane] = (a0 + a1) + (a2 + a3);
    }
}

// pair: smem-staged (BN'd e0 row + up row), packed weights, no shfl
__global__ void convcat_pair(const float* __restrict__ fA, const float* __restrict__ fB,
                             const float* __restrict__ g0, const float* __restrict__ b0,
                             float* __restrict__ out, const int2* __restrict__ pairs,
                             const unsigned char* __restrict__ pk, const int* __restrict__ npp,
                             float inv_n) {
    __shared__ __align__(16) float sx[8][2][64];
    int wid = threadIdx.x >> 5;
    int lane = threadIdx.x & 31;
    int gw = (blockIdx.x * blockDim.x + threadIdx.x) >> 5;
    int nw = (gridDim.x * blockDim.x) >> 5;
    int np = *npp;
    float mu = g_bn[lane] * inv_n;
    float var = g_bn[64 + lane] * inv_n - mu * mu;
    float rs = rsqrtf(var + BN_EPS) * __ldg(&g0[lane]);
    float bb = __ldg(&b0[lane]);
    unsigned long long w[32];
    int kcur = -1;
    const int PPW = 32;
    for (int base = gw * PPW; base < np; base += nw * PPW) {
        int cnt = min(PPW, np - base);
        int2 pr = pairs[base];
        int k = pk[base];
        float fa = __ldg(&fA[(long)pr.y * 32 + lane]);
        float fb = __ldg(&fB[(long)pr.y * 32 + lane]);
        for (int m = 0; m < cnt; m++) {
            int2 prn = make_int2(0, 0); int kn = 0; float fan = 0.f, fbn = 0.f;
            if (m + 1 < cnt) {
                prn = pairs[base + m + 1];
                kn = pk[base + m + 1];
                fan = __ldg(&fA[(long)prn.y * 32 + lane]);
                fbn = __ldg(&fB[(long)prn.y * 32 + lane]);
            }
            if (k != kcur) {
                kcur = k;
                #pragma unroll
                for (int cp = 0; cp < 32; cp++) {
                    float2 wv = __ldg(&g_wpd[(k * 32 + cp) * 32 + lane]);
                    w[cp] = pk2(wv.x, wv.y);
                }
            }
            float fav = (fa - mu) * rs + bb;
            fav = fav > 0.f ? fav : 0.f;
            int buf = m & 1;
            sx[wid][buf][lane] = fav;
            sx[wid][buf][32 + lane] = fb;
            __syncwarp();
            const float4* xs = (const float4*)sx[wid][buf];
            unsigned long long c0 = pk2(0.f, 0.f), c1 = pk2(0.f, 0.f);
            #pragma unroll
            for (int c = 0; c < 16; c++) {
                float4 x = xs[c];
                c0 = fma2(pk2(x.x, x.y), w[2 * c], c0);
                c1 = fma2(pk2(x.z, x.w), w[2 * c + 1], c1);
            }
            float lo, hi; unpk2(add2(c0, c1), lo, hi);
            atomicAdd(&out[(long)pr.x * 32 + lane], lo + hi);
            pr = prn; k = kn; fa = fan; fb = fbn;
        }
    }
}

// ---------------- down: segment_sum(bnrelu(e0) @ W_down[coff], parent) -------
__global__ void down_smem(const float* __restrict__ e0, const int* __restrict__ parent,
                          const int* __restrict__ coff, const float* __restrict__ Wd,
                          const float* __restrict__ g0, const float* __restrict__ b0,
                          float* __restrict__ down, int n, float inv_n) {
    extern __shared__ float sw[];
    for (int j = threadIdx.x; j < 8 * 2048 / 4; j += blockDim.x)
        ((float4*)sw)[j] = ((const float4*)Wd)[j];
    __syncthreads();
    int gw = (blockIdx.x * blockDim.x + threadIdx.x) >> 5;
    int lane = threadIdx.x & 31;
    int nw = (gridDim.x * blockDim.x) >> 5;
    float mu = g_bn[lane] * inv_n;
    float var = g_bn[64 + lane] * inv_n - mu * mu;
    float rs = rsqrtf(var + BN_EPS) * __ldg(&g0[lane]);
    float bb = __ldg(&b0[lane]);
    for (int v = gw; v < n; v += nw) {
        float f = (__ldg(&e0[(long)v * 32 + lane]) - mu) * rs + bb;
        f = f > 0.f ? f : 0.f;
        const float* Wc = sw + coff[v] * 2048;
        unsigned long long a0 = pk2(0.f, 0.f), a1 = pk2(0.f, 0.f);
        #pragma unroll
        for (int c = 0; c < 16; c++) {
            float x0 = __shfl_sync(FULLM, f, 2 * c);
            float x1 = __shfl_sync(FULLM, f, 2 * c + 1);
            float2 w0 = *(const float2*)(Wc + (2 * c) * 64 + 2 * lane);
            float2 w1 = *(const float2*)(Wc + (2 * c + 1) * 64 + 2 * lane);
            a0 = fma2(pk2(x0, x0), pk2(w0.x, w0.y), a0);
            a1 = fma2(pk2(x1, x1), pk2(w1.x, w1.y), a1);
        }
        float r0, r1; unpk2(add2(a0, a1), r0, r1);
        red2(down + (long)parent[v] * 64 + 2 * lane, r0, r1);
    }
}

// ---------------- up: bnrelu(e1)[parent] @ W_up[coff] ------------------------
__global__ void up_smem(const float* __restrict__ e1, const int* __restrict__ parent,
                        const int* __restrict__ coff, const float* __restrict__ Wu,
                        const float* __restrict__ g1, const float* __restrict__ b1,
                        float* __restrict__ up, int n, float inv_m) {
    extern __shared__ float sw[];
    for (int j = threadIdx.x; j < 8 * 2048 / 4; j += blockDim.x)
        ((float4*)sw)[j] = ((const float4*)Wu)[j];
    __syncthreads();
    int gw = (blockIdx.x * blockDim.x + threadIdx.x) >> 5;
    int lane = threadIdx.x & 31;
    int nw = (gridDim.x * blockDim.x) >> 5;
    float muA = g_bn[128 + lane] * inv_m;
    float vaA = g_bn[128 + 64 + lane] * inv_m - muA * muA;
    float rsA = rsqrtf(vaA + BN_EPS) * __ldg(&g1[lane]);
    float bbA = __ldg(&b1[lane]);
    float muB = g_bn[128 + 32 + lane] * inv_m;
    float vaB = g_bn[128 + 64 + 32 + lane] * inv_m - muB * muB;
    float rsB = rsqrtf(vaB + BN_EPS) * __ldg(&g1[32 + lane]);
    float bbB = __ldg(&b1[32 + lane]);
    for (int v = gw; v < n; v += nw) {
        int p = parent[v];
        float f0 = (__ldg(&e1[(long)p * 64 + lane]) - muA) * rsA + bbA;
        f0 = f0 > 0.f ? f0 : 0.f;
        float f1 = (__ldg(&e1[(long)p * 64 + 32 + lane]) - muB) * rsB + bbB;
        f1 = f1 > 0.f ? f1 : 0.f;
        const float* Wc = sw + coff[v] * 2048;
        float a0 = 0.f, a1 = 0.f, a2 = 0.f, a3 = 0.f;
        #pragma unroll
        for (int c = 0; c < 8; c++) {
            a0 = fmaf(__shfl_sync(FULLM, f0, 4 * c + 0), Wc[(4 * c + 0) * 32 + lane], a0);
            a1 = fmaf(__shfl_sync(FULLM, f0, 4 * c + 1), Wc[(4 * c + 1) * 32 + lane], a1);
            a2 = fmaf(__shfl_sync(FULLM, f0, 4 * c + 2), Wc[(4 * c + 2) * 32 + lane], a2);
            a3 = fmaf(__shfl_sync(FULLM, f0, 4 * c + 3), Wc[(4 * c + 3) * 32 + lane], a3);
        }
        #pragma unroll
        for (int c = 0; c < 8; c++) {
            a0 = fmaf(__shfl_sync(FULLM, f1, 4 * c + 0), Wc[(32 + 4 * c + 0) * 32 + lane], a0);
            a1 = fmaf(__shfl_sync(FULLM, f1, 4 * c + 1), Wc[(32 + 4 * c + 1) * 32 + lane], a1);
            a2 = fmaf(__shfl_sync(FULLM, f1, 4 * c + 2), Wc[(32 + 4 * c + 2) * 32 + lane], a2);
            a3 = fmaf(__shfl_sync(FULLM, f1, 4 * c + 3), Wc[(32 + 4 * c + 3) * 32 + lane], a3);
        }
        up[(long)v * 32 + lane] = (a0 + a1) + (a2 + a3);
    }
}

// ---------------- batchnorm stats (float4) -----------------------------------
__global__ void bn_stats(const float* __restrict__ x, int bnid, int C, int n) {
    int C4 = C >> 2;
    int tid = threadIdx.x;
    int c4 = tid & (C4 - 1);
    int rpb = blockDim.x / C4;
    float s0 = 0, s1 = 0, s2 = 0, s3 = 0, q0 = 0, q1 = 0, q2 = 0, q3 = 0;
    for (long r = (long)blockIdx.x * rpb + tid / C4; r < n; r += (long)gridDim.x * rpb) {
        float4 v = *(const float4*)(x + r * C + c4 * 4);
        s0 += v.x; q0 += v.x * v.x;
        s1 += v.y; q1 += v.y * v.y;
        s2 += v.z; q2 += v.z * v.z;
        s3 += v.w; q3 += v.w * v.w;
    }
    __shared__ float ss[64], sq[64];
    if (tid < 64) { ss[tid] = 0.f; sq[tid] = 0.f; }
    __syncthreads();
    int cb = c4 * 4;
    atomicAdd(&ss[cb], s0); atomicAdd(&ss[cb + 1], s1);
    atomicAdd(&ss[cb + 2], s2); atomicAdd(&ss[cb + 3], s3);
    atomicAdd(&sq[cb], q0); atomicAdd(&sq[cb + 1], q1);
    atomicAdd(&sq[cb + 2], q2); atomicAdd(&sq[cb + 3], q3);
    __syncthreads();
    if (tid < C) {
        atomicAdd(&g_bn[bnid * 128 + tid], ss[tid]);
        atomicAdd(&g_bn[bnid * 128 + 64 + tid], sq[tid]);
    }
}

// ---------------- final: bnrelu(dec) -> feature; y = feature@W_lin + b ------
__global__ void final_kernel(const float* __restrict__ dec, const float* __restrict__ g,
                             const float* __restrict__ b, const float* __restrict__ Wlin,
                             const float* __restrict__ blin, float* __restrict__ y,
                             float* __restrict__ fout, int n) {
    int gw = (blockIdx.x * blockDim.x + threadIdx.x) >> 5;
    int lane = threadIdx.x & 31;
    int nw = (gridDim.x * blockDim.x) >> 5;
    float wl[32];
    #pragma unroll
    for (int ci = 0; ci < 32; ci++) wl[ci] = (lane < 20) ? __ldg(&Wlin[ci * 20 + lane]) : 0.f;
    float bl = (lane < 20) ? __ldg(&blin[lane]) : 0.f;
    float inv_n = 1.0f / (float)n;
    float mu = g_bn[2 * 128 + lane] * inv_n;
    float var = g_bn[2 * 128 + 64 + lane] * inv_n - mu * mu;
    float rs = rsqrtf(var + BN_EPS) * __ldg(&g[lane]);
    float br = __ldg(&b[lane]);
    for (int v = gw; v < n; v += nw) {
        float f = (__ldg(&dec[(long)v * 32 + lane]) - mu) * rs + br;
        f = f > 0.f ? f : 0.f;
        fout[(long)v * 32 + lane] = f;
        float a0 = bl, a1 = 0.f;
        #pragma unroll
        for (int c = 0; c < 16; c++) {
            a0 = fmaf(__shfl_sync(FULLM, f, 2 * c), wl[2 * c], a0);
            a1 = fmaf(__shfl_sync(FULLM, f, 2 * c + 1), wl[2 * c + 1], a1);
        }
        if (lane < 20) y[(long)v * 20 + lane] = a0 + a1;
    }
}

// ---------------- launcher ---------------------------------------------------
extern "C" void kernel_launch(void* const* d_in, const int* in_sizes, int n_in,
                              void* d_out, int out_size) {
    const float* feats      = (const float*)d_in[0];
    const int*   nbr_fine   = (const int*)  d_in[1];
    const int*   nbr_coarse = (const int*)  d_in[2];
    const int*   parent     = (const int*)  d_in[3];
    const int*   coff       = (const int*)  d_in[4];
    const float* W_sub      = (const float*)d_in[5];
    const float* W_e0       = (const float*)d_in[6];
    const float* g0         = (const float*)d_in[7];
    const float* b0         = (const float*)d_in[8];
    const float* W_down     = (const float*)d_in[9];
    const float* W_e1       = (const float*)d_in[10];
    const float* g1         = (const float*)d_in[11];
    const float* b1         = (const float*)d_in[12];
    const float* W_up       = (const float*)d_in[13];
    const float* W_dec      = (const float*)d_in[14];
    const float* g_outp     = (const float*)d_in[15];
    const float* b_outp     = (const float*)d_in[16];
    const float* W_lin      = (const float*)d_in[17];
    const float* b_lin      = (const float*)d_in[18];

    int N = in_sizes[0] / 3;
    int M = in_sizes[2] / 27;
    float inv_n = 1.0f / (float)N;
    float inv_m = 1.0f / (float)M;

    float* y    = (float*)d_out;
    float* fout = y + (long)N * 20;

    float *p_xv, *p_e0, *p_down, *p_e1, *p_up, *p_dec;
    int2 *p_pf, *p_pc; unsigned char *p_pfk, *p_pck; int *p_np;
    cudaGetSymbolAddress((void**)&p_xv,   g_xv);
    cudaGetSymbolAddress((void**)&p_e0,   g_e0);
    cudaGetSymbolAddress((void**)&p_down, g_down);
    cudaGetSymbolAddress((void**)&p_e1,   g_e1);
    cudaGetSymbolAddress((void**)&p_up,   g_up);
    cudaGetSymbolAddress((void**)&p_dec,  g_dec);
    cudaGetSymbolAddress((void**)&p_pf,   g_pf);
    cudaGetSymbolAddress((void**)&p_pc,   g_pc);
    cudaGetSymbolAddress((void**)&p_pfk,  g_pfk);
    cudaGetSymbolAddress((void**)&p_pck,  g_pck);
    cudaGetSymbolAddress((void**)&p_np,   g_np);

    cudaFuncSetAttribute(down_smem, cudaFuncAttributeMaxDynamicSharedMemorySize, 65536);
    cudaFuncSetAttribute(up_smem,   cudaFuncAttributeMaxDynamicSharedMemorySize, 65536);

    dim3 b256(256), b128(128);
    int GP = 1024;      // persistent grids (256 thr)
    int GH = 2048;      // conv64 kernels (128 thr)
    int GD = 444;       // 64KB-smem kernels

    pack_weights<<<(27 * 32 * 64 + 255) / 256, b256>>>(W_e0, W_e1, W_dec);
    zero_kernel<<<1024, b256>>>(M);

    // single-pass pair build (block-chunk reservation; k-major within chunk)
    int tilesF = (N + FILL_VPB - 1) / FILL_VPB;
    int tilesC = (M + FILL_VPB - 1) / FILL_VPB;
    fill_kernel<<<tilesF + tilesC, b256>>>(nbr_fine, N, tilesF, nbr_coarse, M);

    // encoder fine level
    conv3_center<<<GP, b256>>>(feats, W_sub, p_xv, N);
    conv3_pair  <<<GP, b256>>>(feats, W_sub, p_xv, p_pf, p_pfk, p_np + 0);
    conv32_center<<<GP, b256>>>(p_xv, W_e0, p_e0, N);
    conv32_pair  <<<GP, b256>>>(p_xv, p_e0, p_pf, p_pfk, p_np + 0);
    bn_stats<<<GP, b256>>>(p_e0, 0, 32, N);

    // down + coarse level (BN0 applied inline)
    down_smem<<<GD, b256, 65536>>>(p_e0, parent, coff, W_down, g0, b0, p_down, N, inv_n);
    conv64_center<<<GH, b128>>>(p_down, W_e1, p_e1, M);
    conv64_pair  <<<GH, b128>>>(p_down, p_e1, p_pc, p_pck, p_np + 1);
    bn_stats<<<GP, b256>>>(p_e1, 1, 64, M);

    // up + decoder (BN1 / BN0 applied inline)
    up_smem<<<GD, b256, 65536>>>(p_e1, parent, coff, W_up, g1, b1, p_up, N, inv_m);
    convcat_center<<<GP, b256>>>(p_e0, p_up, W_dec, g0, b0, p_dec, N, inv_n);
    convcat_pair  <<<GP, b256>>>(p_e0, p_up, g0, b0, p_dec, p_pf, p_pfk, p_np + 0, inv_n);
    bn_stats<<<GP, b256>>>(p_dec, 2, 32, N);

    // fused bnrelu + linear head, writes both outputs
    final_kernel<<<GP, b256>>>(p_dec, g_outp, b_outp, W_lin, b_lin, y, fout, N);
}

// round 17
// speedup vs baseline: 1.4952x; 1.4952x over previous
#include <cuda_runtime.h>

#define MAXN 400000
#define MAXPAIR (MAXN * 26)
#define BN_EPS 1e-4f
#define FULLM 0xffffffffu

// ---------------- scratch (device globals; no allocations allowed) ----------
__device__ float g_xv  [(size_t)MAXN * 32];
__device__ float g_e0  [(size_t)MAXN * 32];
__device__ float g_down[(size_t)MAXN * 64];
__device__ float g_e1  [(size_t)MAXN * 64];
__device__ float g_up  [(size_t)MAXN * 32];
__device__ float g_dec [(size_t)MAXN * 32];
__device__ float g_bn[3 * 128];            // per-bn: [0:64) sums, [64:128) sumsq

__device__ int2          g_pf [MAXPAIR];   // fine pairs (dst, src)
__device__ unsigned char g_pfk[MAXPAIR];
__device__ int2          g_pc [MAXPAIR];   // coarse pairs
__device__ unsigned char g_pck[MAXPAIR];
__device__ int g_np[2];                    // pair-list totals
__device__ int g_wcur[4];                  // dynamic window cursors (per pair kernel)

// packed weights: (ci-pair) x cout layout so LDS.128 feature reads feed FFMA2
__device__ float2 g_wp0[27 * 16 * 32];
__device__ float4 g_wp1q[27 * 32 * 32];
__device__ float2 g_wpd[27 * 32 * 32];

// ---------------- f32x2 helpers ---------------------------------------------
__device__ __forceinline__ unsigned long long pk2(float x, float y) {
    unsigned long long r;
    asm("mov.b64 %0, {%1, %2};" : "=l"(r) : "f"(x), "f"(y));
    return r;
}
__device__ __forceinline__ unsigned long long fma2(unsigned long long a,
                                                   unsigned long long b,
                                                   unsigned long long c) {
    unsigned long long d;
    asm("fma.rn.f32x2 %0, %1, %2, %3;" : "=l"(d) : "l"(a), "l"(b), "l"(c));
    return d;
}
__device__ __forceinline__ void unpk2(unsigned long long a, float& x, float& y) {
    asm("mov.b64 {%0, %1}, %2;" : "=f"(x), "=f"(y) : "l"(a));
}
__device__ __forceinline__ unsigned long long add2(unsigned long long a,
                                                   unsigned long long b) {
    unsigned long long d;
    asm("add.rn.f32x2 %0, %1, %2;" : "=l"(d) : "l"(a), "l"(b));
    return d;
}
__device__ __forceinline__ void red2(float* p, float x, float y) {
    asm volatile("red.global.add.v2.f32 [%0], {%1, %2};" :: "l"(p), "f"(x), "f"(y));
}

// ---------------- weight packing (once per launch, ~775KB) ------------------
__global__ void pack_weights(const float* __restrict__ W0, const float* __restrict__ W1,
                             const float* __restrict__ Wd) {
    int t = blockIdx.x * blockDim.x + threadIdx.x;
    if (t < 27 * 16 * 32) {
        int k = t / 512, r = t % 512, cp = r / 32, co = r % 32;
        g_wp0[t] = make_float2(W0[(k * 32 + 2 * cp) * 32 + co],
                               W0[(k * 32 + 2 * cp + 1) * 32 + co]);
    }
    if (t < 27 * 32 * 32) {
        int k = t / 1024, r = t % 1024, cp = r / 32, cq = r % 32;
        const float* b0 = W1 + (long)(k * 64 + 2 * cp) * 64;
        const float* b1 = W1 + (long)(k * 64 + 2 * cp + 1) * 64;
        g_wp1q[t] = make_float4(b0[2 * cq], b1[2 * cq], b0[2 * cq + 1], b1[2 * cq + 1]);
        g_wpd[t] = make_float2(Wd[(k * 64 + 2 * cp) * 32 + cq],
                               Wd[(k * 64 + 2 * cp + 1) * 32 + cq]);
    }
}

// ---------------- zero: g_down rows, bn accumulators, cursors ---------------
__global__ void zero_kernel(int m) {
    int tid = blockIdx.x * blockDim.x + threadIdx.x;
    int stride = gridDim.x * blockDim.x;
    float4* d4 = (float4*)g_down;
    int n4 = m * 16;
    for (int i = tid; i < n4; i += stride) d4[i] = make_float4(0.f, 0.f, 0.f, 0.f);
    if (blockIdx.x == 0 && threadIdx.x < 128) {
        g_bn[threadIdx.x] = 0.f; g_bn[128 + threadIdx.x] = 0.f; g_bn[256 + threadIdx.x] = 0.f;
        if (threadIdx.x < 2) g_np[threadIdx.x] = 0;
        if (threadIdx.x < 4) g_wcur[threadIdx.x] = 0;
    }
}

// ---------------- single-pass pair building ---------------------------------
#define FILL_VPB 256
__global__ void fill_kernel(const int* __restrict__ nbrF, int nF, int tilesF,
                            const int* __restrict__ nbrC, int nC) {
    int lvl, t0, nv;
    const int* nbr;
    int2* pairs; unsigned char* pkk;
    if ((int)blockIdx.x < tilesF) {
        lvl = 0; t0 = blockIdx.x * FILL_VPB; nbr = nbrF; nv = nF; pairs = g_pf; pkk = g_pfk;
    } else {
        lvl = 1; t0 = (blockIdx.x - tilesF) * FILL_VPB; nbr = nbrC; nv = nC; pairs = g_pc; pkk = g_pck;
    }
    int v = t0 + threadIdx.x;
    __shared__ int cnt[27], cur[27];
    __shared__ int sbase;
    if (threadIdx.x < 27) cnt[threadIdx.x] = 0;
    __syncthreads();
    if (v < nv) {
        const int* row = nbr + (long)v * 27;
        #pragma unroll
        for (int k = 0; k < 27; k++) {
            if (k == 13) continue;
            if (row[k] >= 0) atomicAdd(&cnt[k], 1);
        }
    }
    __syncthreads();
    if (threadIdx.x < 32) {
        int k = threadIdx.x;
        int c = (k < 27) ? cnt[k] : 0;
        int s = c;
        #pragma unroll
        for (int d = 1; d < 32; d <<= 1) {
            int t = __shfl_up_sync(FULLM, s, d);
            if (k >= d) s += t;
        }
        if (k == 26) sbase = atomicAdd(&g_np[lvl], s);
        if (k < 27) cur[k] = s - c;
    }
    __syncthreads();
    if (threadIdx.x < 27) cur[threadIdx.x] += sbase;
    __syncthreads();
    if (v < nv) {
        const int* row = nbr + (long)v * 27;
        #pragma unroll
        for (int k = 0; k < 27; k++) {
            if (k == 13) continue;
            int idx = row[k];
            if (idx >= 0) {
                int pos = atomicAdd(&cur[k], 1);
                pairs[pos] = make_int2(v, idx);
                pkk[pos] = (unsigned char)k;
            }
        }
    }
}

// dynamic window grab: lane0 atomics a window base, broadcast to warp
__device__ __forceinline__ int grab_window(int* cursor, int lane, int ppw) {
    int base = 0;
    if (lane == 0) base = atomicAdd(cursor, ppw);
    return __shfl_sync(FULLM, base, 0);
}

// ---------------- conv 3->32 -------------------------------------------------
__global__ void conv3_center(const float* __restrict__ in, const float* __restrict__ W,
                             float* __restrict__ out, int n) {
    int gw = (blockIdx.x * blockDim.x + threadIdx.x) >> 5;
    int lane = threadIdx.x & 31;
    int nw = (gridDim.x * blockDim.x) >> 5;
    float w0 = __ldg(&W[(13 * 3 + 0) * 32 + lane]);
    float w1 = __ldg(&W[(13 * 3 + 1) * 32 + lane]);
    float w2 = __ldg(&W[(13 * 3 + 2) * 32 + lane]);
    for (int v = gw; v < n; v += nw) {
        float f = (lane < 3) ? __ldg(&in[(long)v * 3 + lane]) : 0.f;
        float a = __shfl_sync(FULLM, f, 0) * w0;
        a = fmaf(__shfl_sync(FULLM, f, 1), w1, a);
        a = fmaf(__shfl_sync(FULLM, f, 2), w2, a);
        out[(long)v * 32 + lane] = a;
    }
}

__global__ void conv3_pair(const float* __restrict__ in, const float* __restrict__ W,
                           float* __restrict__ out, const int2* __restrict__ pairs,
                           const unsigned char* __restrict__ pk, const int* __restrict__ npp) {
    int gw = (blockIdx.x * blockDim.x + threadIdx.x) >> 5;
    int lane = threadIdx.x & 31;
    int nw = (gridDim.x * blockDim.x) >> 5;
    int np = *npp;
    float w0 = 0.f, w1 = 0.f, w2 = 0.f;
    int kcur = -1;
    const int PPW = 32;
    for (int base = gw * PPW; base < np; base += nw * PPW) {
        int cnt = min(PPW, np - base);
        int2 pr = pairs[base];
        int k = pk[base];
        float f = (lane < 3) ? __ldg(&in[(long)pr.y * 3 + lane]) : 0.f;
        for (int m = 0; m < cnt; m++) {
            int2 prn = make_int2(0, 0); int kn = 0; float fn = 0.f;
            if (m + 1 < cnt) {
                prn = pairs[base + m + 1];
                kn = pk[base + m + 1];
                fn = (lane < 3) ? __ldg(&in[(long)prn.y * 3 + lane]) : 0.f;
            }
            if (k != kcur) {
                kcur = k;
                w0 = __ldg(&W[(k * 3 + 0) * 32 + lane]);
                w1 = __ldg(&W[(k * 3 + 1) * 32 + lane]);
                w2 = __ldg(&W[(k * 3 + 2) * 32 + lane]);
            }
            float a = __shfl_sync(FULLM, f, 0) * w0;
            a = fmaf(__shfl_sync(FULLM, f, 1), w1, a);
            a = fmaf(__shfl_sync(FULLM, f, 2), w2, a);
            atomicAdd(&out[(long)pr.x * 32 + lane], a);
            pr = prn; k = kn; f = fn;
        }
    }
}

// ---------------- conv 32->32 ------------------------------------------------
__global__ void conv32_center(const float* __restrict__ in, const float* __restrict__ W,
                              float* __restrict__ out, int n) {
    int gw = (blockIdx.x * blockDim.x + threadIdx.x) >> 5;
    int lane = threadIdx.x & 31;
    int nw = (gridDim.x * blockDim.x) >> 5;
    float w[32];
    #pragma unroll
    for (int ci = 0; ci < 32; ci++) w[ci] = __ldg(&W[(13 * 32 + ci) * 32 + lane]);
    for (int v = gw; v < n; v += nw) {
        float f = __ldg(&in[(long)v * 32 + lane]);
        float a0 = 0.f, a1 = 0.f, a2 = 0.f, a3 = 0.f;
        #pragma unroll
        for (int c = 0; c < 8; c++) {
            a0 = fmaf(__shfl_sync(FULLM, f, 4 * c + 0), w[4 * c + 0], a0);
            a1 = fmaf(__shfl_sync(FULLM, f, 4 * c + 1), w[4 * c + 1], a1);
            a2 = fmaf(__shfl_sync(FULLM, f, 4 * c + 2), w[4 * c + 2], a2);
            a3 = fmaf(__shfl_sync(FULLM, f, 4 * c + 3), w[4 * c + 3], a3);
        }
        out[(long)v * 32 + lane] = (a0 + a1) + (a2 + a3);
    }
}

// pair: smem-staged broadcast, packed weights, dynamic windows
__global__ void conv32_pair(const float* __restrict__ in, float* __restrict__ out,
                            const int2* __restrict__ pairs,
                            const unsigned char* __restrict__ pk, const int* __restrict__ npp) {
    __shared__ __align__(16) float sx[8][2][32];
    int wid = threadIdx.x >> 5;
    int lane = threadIdx.x & 31;
    int np = *npp;
    unsigned long long w[16];
    int kcur = -1;
    const int PPW = 32;
    for (;;) {
        int base = grab_window(&g_wcur[1], lane, PPW);
        if (base >= np) break;
        int cnt = min(PPW, np - base);
        int2 pr = pairs[base];
        int k = pk[base];
        float f = __ldg(&in[(long)pr.y * 32 + lane]);
        for (int m = 0; m < cnt; m++) {
            int2 prn = make_int2(0, 0); int kn = 0; float fn = 0.f;
            if (m + 1 < cnt) {
                prn = pairs[base + m + 1];
                kn = pk[base + m + 1];
                fn = __ldg(&in[(long)prn.y * 32 + lane]);
            }
            if (k != kcur) {
                kcur = k;
                #pragma unroll
                for (int cp = 0; cp < 16; cp++) {
                    float2 wv = __ldg(&g_wp0[(k * 16 + cp) * 32 + lane]);
                    w[cp] = pk2(wv.x, wv.y);
                }
            }
            int buf = m & 1;
            sx[wid][buf][lane] = f;
            __syncwarp();
            const float4* xs = (const float4*)sx[wid][buf];
            unsigned long long c0 = pk2(0.f, 0.f), c1 = pk2(0.f, 0.f);
            #pragma unroll
            for (int c = 0; c < 8; c++) {
                float4 x = xs[c];
                c0 = fma2(pk2(x.x, x.y), w[2 * c], c0);
                c1 = fma2(pk2(x.z, x.w), w[2 * c + 1], c1);
            }
            float lo, hi; unpk2(add2(c0, c1), lo, hi);
            atomicAdd(&out[(long)pr.x * 32 + lane], lo + hi);
            pr = prn; k = kn; f = fn;
        }
    }
}

// ---------------- conv 64->64 (coarse) ---------------------------------------
__global__ void __launch_bounds__(128)
conv64_center(const float* __restrict__ in, const float* __restrict__ W,
              float* __restrict__ out, int n) {
    int gw = (blockIdx.x * blockDim.x + threadIdx.x) >> 5;
    int lane = threadIdx.x & 31;
    int nw = (gridDim.x * blockDim.x) >> 5;
    unsigned long long w2[64];
    #pragma unroll
    for (int ci = 0; ci < 64; ci++) {
        float2 wv = *(const float2*)(W + (long)(13 * 64 + ci) * 64 + 2 * lane);
        w2[ci] = pk2(wv.x, wv.y);
    }
    for (int v = gw; v < n; v += nw) {
        float2 fv = *(const float2*)(in + (long)v * 64 + 2 * lane);
        unsigned long long a0 = pk2(0.f, 0.f), a1 = pk2(0.f, 0.f);
        unsigned long long a2 = pk2(0.f, 0.f), a3 = pk2(0.f, 0.f);
        #pragma unroll
        for (int j = 0; j < 16; j++) {
            float va0 = __shfl_sync(FULLM, fv.x, 2 * j);
            float vb0 = __shfl_sync(FULLM, fv.y, 2 * j);
            float va1 = __shfl_sync(FULLM, fv.x, 2 * j + 1);
            float vb1 = __shfl_sync(FULLM, fv.y, 2 * j + 1);
            a0 = fma2(pk2(va0, va0), w2[4 * j + 0], a0);
            a1 = fma2(pk2(vb0, vb0), w2[4 * j + 1], a1);
            a2 = fma2(pk2(va1, va1), w2[4 * j + 2], a2);
            a3 = fma2(pk2(vb1, vb1), w2[4 * j + 3], a3);
        }
        float r0, r1; unpk2(add2(add2(a0, a1), add2(a2, a3)), r0, r1);
        *(float2*)(out + (long)v * 64 + 2 * lane) = make_float2(r0, r1);
    }
}

// pair: smem-staged LDS.128 + packed weights; dynamic windows; PPW=32
__global__ void __launch_bounds__(128)
conv64_pair(const float* __restrict__ in, float* __restrict__ out,
            const int2* __restrict__ pairs,
            const unsigned char* __restrict__ pk, const int* __restrict__ npp) {
    __shared__ __align__(16) float sx[4][2][64];
    int wid = threadIdx.x >> 5;
    int lane = threadIdx.x & 31;
    int np = *npp;
    unsigned long long wa[32], wb[32];
    int kcur = -1;
    const int PPW = 32;
    for (;;) {
        int base = grab_window(&g_wcur[0], lane, PPW);
        if (base >= np) break;
        int cnt = min(PPW, np - base);
        int2 pr = pairs[base];
        int k = pk[base];
        float2 fv = *(const float2*)(in + (long)pr.y * 64 + 2 * lane);
        for (int m = 0; m < cnt; m++) {
            int2 prn = make_int2(0, 0); int kn = 0; float2 fvn = make_float2(0.f, 0.f);
            if (m + 1 < cnt) {
                prn = pairs[base + m + 1];
                kn = pk[base + m + 1];
                fvn = *(const float2*)(in + (long)prn.y * 64 + 2 * lane);
            }
            if (k != kcur) {
                kcur = k;
                #pragma unroll
                for (int cp = 0; cp < 32; cp++) {
                    float4 wv = __ldg(&g_wp1q[(k * 32 + cp) * 32 + lane]);
                    wa[cp] = pk2(wv.x, wv.y);
                    wb[cp] = pk2(wv.z, wv.w);
                }
            }
            int buf = m & 1;
            *(float2*)&sx[wid][buf][2 * lane] = fv;
            __syncwarp();
            const float4* xs = (const float4*)sx[wid][buf];
            unsigned long long a0 = pk2(0.f, 0.f), a1 = pk2(0.f, 0.f);
            unsigned long long b0 = pk2(0.f, 0.f), b1 = pk2(0.f, 0.f);
            #pragma unroll
            for (int c = 0; c < 16; c++) {
                float4 x = xs[c];
                unsigned long long xp0 = pk2(x.x, x.y);
                unsigned long long xp1 = pk2(x.z, x.w);
                a0 = fma2(xp0, wa[2 * c], a0);
                b0 = fma2(xp0, wb[2 * c], b0);
                a1 = fma2(xp1, wa[2 * c + 1], a1);
                b1 = fma2(xp1, wb[2 * c + 1], b1);
            }
            float al, ah, bl, bh;
            unpk2(add2(a0, a1), al, ah);
            unpk2(add2(b0, b1), bl, bh);
            red2(out + (long)pr.x * 64 + 2 * lane, al + ah, bl + bh);
            pr = prn; k = kn; fv = fvn;
        }
    }
}

// ---------------- conv concat(bnrelu(e0) + up)->32 (decoder) -----------------
__global__ void convcat_center(const float* __restrict__ fA, const float* __restrict__ fB,
                               const float* __restrict__ W,
                               const float* __restrict__ g0, const float* __restrict__ b0,
                               float* __restrict__ out, int n, float inv_n) {
    int gw = (blockIdx.x * blockDim.x + threadIdx.x) >> 5;
    int lane = threadIdx.x & 31;
    int nw = (gridDim.x * blockDim.x) >> 5;
    float mu = g_bn[lane] * inv_n;
    float var = g_bn[64 + lane] * inv_n - mu * mu;
    float rs = rsqrtf(var + BN_EPS) * __ldg(&g0[lane]);
    float bb = __ldg(&b0[lane]);
    float w[64];
    #pragma unroll
    for (int ci = 0; ci < 64; ci++) w[ci] = __ldg(&W[(13 * 64 + ci) * 32 + lane]);
    for (int v = gw; v < n; v += nw) {
        float fa = (__ldg(&fA[(long)v * 32 + lane]) - mu) * rs + bb;
        fa = fa > 0.f ? fa : 0.f;
        float fb = __ldg(&fB[(long)v * 32 + lane]);
        float a0 = 0.f, a1 = 0.f, a2 = 0.f, a3 = 0.f;
        #pragma unroll
        for (int c = 0; c < 8; c++) {
            a0 = fmaf(__shfl_sync(FULLM, fa, 4 * c + 0), w[4 * c + 0], a0);
            a1 = fmaf(__shfl_sync(FULLM, fa, 4 * c + 1), w[4 * c + 1], a1);
            a2 = fmaf(__shfl_sync(FULLM, fa, 4 * c + 2), w[4 * c + 2], a2);
            a3 = fmaf(__shfl_sync(FULLM, fa, 4 * c + 3), w[4 * c + 3], a3);
        }
        #pragma unroll
        for (int c = 0; c < 8; c++) {
            a0 = fmaf(__shfl_sync(FULLM, fb, 4 * c + 0), w[32 + 4 * c + 0], a0);
            a1 = fmaf(__shfl_sync(FULLM, fb, 4 * c + 1), w[32 + 4 * c + 1], a1);
            a2 = fmaf(__shfl_sync(FULLM, fb, 4 * c + 2), w[32 + 4 * c + 2], a2);
            a3 = fmaf(__shfl_sync(FULLM, fb, 4 * c + 3), w[32 + 4 * c + 3], a3);
        }
        out[(long)v * 32 + lane] = (a0 + a1) + (a2 + a3);
    }
}

// pair: smem-staged, packed weights, dynamic windows
__global__ void convcat_pair(const float* __restrict__ fA, const float* __restrict__ fB,
                             const float* __restrict__ g0, const float* __restrict__ b0,
                             float* __restrict__ out, const int2* __restrict__ pairs,
                             const unsigned char* __restrict__ pk, const int* __restrict__ npp,
                             float inv_n) {
    __shared__ __align__(16) float sx[8][2][64];
    int wid = threadIdx.x >> 5;
    int lane = threadIdx.x & 31;
    int np = *npp;
    float mu = g_bn[lane] * inv_n;
    float var = g_bn[64 + lane] * inv_n - mu * mu;
    float rs = rsqrtf(var + BN_EPS) * __ldg(&g0[lane]);
    float bb = __ldg(&b0[lane]);
    unsigned long long w[32];
    int kcur = -1;
    const int PPW = 32;
    for (;;) {
        int base = grab_window(&g_wcur[2], lane, PPW);
        if (base >= np) break;
        int cnt = min(PPW, np - base);
        int2 pr = pairs[base];
        int k = pk[base];
        float fa = __ldg(&fA[(long)pr.y * 32 + lane]);
        float fb = __ldg(&fB[(long)pr.y * 32 + lane]);
        for (int m = 0; m < cnt; m++) {
            int2 prn = make_int2(0, 0); int kn = 0; float fan = 0.f, fbn = 0.f;
            if (m + 1 < cnt) {
                prn = pairs[base + m + 1];
                kn = pk[base + m + 1];
                fan = __ldg(&fA[(long)prn.y * 32 + lane]);
                fbn = __ldg(&fB[(long)prn.y * 32 + lane]);
            }
            if (k != kcur) {
                kcur = k;
                #pragma unroll
                for (int cp = 0; cp < 32; cp++) {
                    float2 wv = __ldg(&g_wpd[(k * 32 + cp) * 32 + lane]);
                    w[cp] = pk2(wv.x, wv.y);
                }
            }
            float fav = (fa - mu) * rs + bb;
            fav = fav > 0.f ? fav : 0.f;
            int buf = m & 1;
            sx[wid][buf][lane] = fav;
            sx[wid][buf][32 + lane] = fb;
            __syncwarp();
            const float4* xs = (const float4*)sx[wid][buf];
            unsigned long long c0 = pk2(0.f, 0.f), c1 = pk2(0.f, 0.f);
            #pragma unroll
            for (int c = 0; c < 16; c++) {
                float4 x = xs[c];
                c0 = fma2(pk2(x.x, x.y), w[2 * c], c0);
                c1 = fma2(pk2(x.z, x.w), w[2 * c + 1], c1);
            }
            float lo, hi; unpk2(add2(c0, c1), lo, hi);
            atomicAdd(&out[(long)pr.x * 32 + lane], lo + hi);
            pr = prn; k = kn; fa = fan; fb = fbn;
        }
    }
}

// ---------------- down: segment_sum(bnrelu(e0) @ W_down[coff], parent) -------
__global__ void down_smem(const float* __restrict__ e0, const int* __restrict__ parent,
                          const int* __restrict__ coff, const float* __restrict__ Wd,
                          const float* __restrict__ g0, const float* __restrict__ b0,
                          float* __restrict__ down, int n, float inv_n) {
    extern __shared__ float sw[];
    for (int j = threadIdx.x; j < 8 * 2048 / 4; j += blockDim.x)
        ((float4*)sw)[j] = ((const float4*)Wd)[j];
    __syncthreads();
    int gw = (blockIdx.x * blockDim.x + threadIdx.x) >> 5;
    int lane = threadIdx.x & 31;
    int nw = (gridDim.x * blockDim.x) >> 5;
    float mu = g_bn[lane] * inv_n;
    float var = g_bn[64 + lane] * inv_n - mu * mu;
    float rs = rsqrtf(var + BN_EPS) * __ldg(&g0[lane]);
    float bb = __ldg(&b0[lane]);
    for (int v = gw; v < n; v += nw) {
        float f = (__ldg(&e0[(long)v * 32 + lane]) - mu) * rs + bb;
        f = f > 0.f ? f : 0.f;
        const float* Wc = sw + coff[v] * 2048;
        unsigned long long a0 = pk2(0.f, 0.f), a1 = pk2(0.f, 0.f);
        #pragma unroll
        for (int c = 0; c < 16; c++) {
            float x0 = __shfl_sync(FULLM, f, 2 * c);
            float x1 = __shfl_sync(FULLM, f, 2 * c + 1);
            float2 w0 = *(const float2*)(Wc + (2 * c) * 64 + 2 * lane);
            float2 w1 = *(const float2*)(Wc + (2 * c + 1) * 64 + 2 * lane);
            a0 = fma2(pk2(x0, x0), pk2(w0.x, w0.y), a0);
            a1 = fma2(pk2(x1, x1), pk2(w1.x, w1.y), a1);
        }
        float r0, r1; unpk2(add2(a0, a1), r0, r1);
        red2(down + (long)parent[v] * 64 + 2 * lane, r0, r1);
    }
}

// ---------------- up: bnrelu(e1)[parent] @ W_up[coff] ------------------------
__global__ void up_smem(const float* __restrict__ e1, const int* __restrict__ parent,
                        const int* __restrict__ coff, const float* __restrict__ Wu,
                        const float* __restrict__ g1, const float* __restrict__ b1,
                        float* __restrict__ up, int n, float inv_m) {
    extern __shared__ float sw[];
    for (int j = threadIdx.x; j < 8 * 2048 / 4; j += blockDim.x)
        ((float4*)sw)[j] = ((const float4*)Wu)[j];
    __syncthreads();
    int gw = (blockIdx.x * blockDim.x + threadIdx.x) >> 5;
    int lane = threadIdx.x & 31;
    int nw = (gridDim.x * blockDim.x) >> 5;
    float muA = g_bn[128 + lane] * inv_m;
    float vaA = g_bn[128 + 64 + lane] * inv_m - muA * muA;
    float rsA = rsqrtf(vaA + BN_EPS) * __ldg(&g1[lane]);
    float bbA = __ldg(&b1[lane]);
    float muB = g_bn[128 + 32 + lane] * inv_m;
    float vaB = g_bn[128 + 64 + 32 + lane] * inv_m - muB * muB;
    float rsB = rsqrtf(vaB + BN_EPS) * __ldg(&g1[32 + lane]);
    float bbB = __ldg(&b1[32 + lane]);
    for (int v = gw; v < n; v += nw) {
        int p = parent[v];
        float f0 = (__ldg(&e1[(long)p * 64 + lane]) - muA) * rsA + bbA;
        f0 = f0 > 0.f ? f0 : 0.f;
        float f1 = (__ldg(&e1[(long)p * 64 + 32 + lane]) - muB) * rsB + bbB;
        f1 = f1 > 0.f ? f1 : 0.f;
        const float* Wc = sw + coff[v] * 2048;
        float a0 = 0.f, a1 = 0.f, a2 = 0.f, a3 = 0.f;
        #pragma unroll
        for (int c = 0; c < 8; c++) {
            a0 = fmaf(__shfl_sync(FULLM, f0, 4 * c + 0), Wc[(4 * c + 0) * 32 + lane], a0);
            a1 = fmaf(__shfl_sync(FULLM, f0, 4 * c + 1), Wc[(4 * c + 1) * 32 + lane], a1);
            a2 = fmaf(__shfl_sync(FULLM, f0, 4 * c + 2), Wc[(4 * c + 2) * 32 + lane], a2);
            a3 = fmaf(__shfl_sync(FULLM, f0, 4 * c + 3), Wc[(4 * c + 3) * 32 + lane], a3);
        }
        #pragma unroll
        for (int c = 0; c < 8; c++) {
            a0 = fmaf(__shfl_sync(FULLM, f1, 4 * c + 0), Wc[(32 + 4 * c + 0) * 32 + lane], a0);
            a1 = fmaf(__shfl_sync(FULLM, f1, 4 * c + 1), Wc[(32 + 4 * c + 1) * 32 + lane], a1);
            a2 = fmaf(__shfl_sync(FULLM, f1, 4 * c + 2), Wc[(32 + 4 * c + 2) * 32 + lane], a2);
            a3 = fmaf(__shfl_sync(FULLM, f1, 4 * c + 3), Wc[(32 + 4 * c + 3) * 32 + lane], a3);
        }
        up[(long)v * 32 + lane] = (a0 + a1) + (a2 + a3);
    }
}

// ---------------- batchnorm stats (float4) -----------------------------------
__global__ void bn_stats(const float* __restrict__ x, int bnid, int C, int n) {
    int C4 = C >> 2;
    int tid = threadIdx.x;
    int c4 = tid & (C4 - 1);
    int rpb = blockDim.x / C4;
    float s0 = 0, s1 = 0, s2 = 0, s3 = 0, q0 = 0, q1 = 0, q2 = 0, q3 = 0;
    for (long r = (long)blockIdx.x * rpb + tid / C4; r < n; r += (long)gridDim.x * rpb) {
        float4 v = *(const float4*)(x + r * C + c4 * 4);
        s0 += v.x; q0 += v.x * v.x;
        s1 += v.y; q1 += v.y * v.y;
        s2 += v.z; q2 += v.z * v.z;
        s3 += v.w; q3 += v.w * v.w;
    }
    __shared__ float ss[64], sq[64];
    if (tid < 64) { ss[tid] = 0.f; sq[tid] = 0.f; }
    __syncthreads();
    int cb = c4 * 4;
    atomicAdd(&ss[cb], s0); atomicAdd(&ss[cb + 1], s1);
    atomicAdd(&ss[cb + 2], s2); atomicAdd(&ss[cb + 3], s3);
    atomicAdd(&sq[cb], q0); atomicAdd(&sq[cb + 1], q1);
    atomicAdd(&sq[cb + 2], q2); atomicAdd(&sq[cb + 3], q3);
    __syncthreads();
    if (tid < C) {
        atomicAdd(&g_bn[bnid * 128 + tid], ss[tid]);
        atomicAdd(&g_bn[bnid * 128 + 64 + tid], sq[tid]);
    }
}

// ---------------- final: bnrelu(dec) -> feature; y = feature@W_lin + b ------
__global__ void final_kernel(const float* __restrict__ dec, const float* __restrict__ g,
                             const float* __restrict__ b, const float* __restrict__ Wlin,
                             const float* __restrict__ blin, float* __restrict__ y,
                             float* __restrict__ fout, int n) {
    int gw = (blockIdx.x * blockDim.x + threadIdx.x) >> 5;
    int lane = threadIdx.x & 31;
    int nw = (gridDim.x * blockDim.x) >> 5;
    float wl[32];
    #pragma unroll
    for (int ci = 0; ci < 32; ci++) wl[ci] = (lane < 20) ? __ldg(&Wlin[ci * 20 + lane]) : 0.f;
    float bl = (lane < 20) ? __ldg(&blin[lane]) : 0.f;
    float inv_n = 1.0f / (float)n;
    float mu = g_bn[2 * 128 + lane] * inv_n;
    float var = g_bn[2 * 128 + 64 + lane] * inv_n - mu * mu;
    float rs = rsqrtf(var + BN_EPS) * __ldg(&g[lane]);
    float br = __ldg(&b[lane]);
    for (int v = gw; v < n; v += nw) {
        float f = (__ldg(&dec[(long)v * 32 + lane]) - mu) * rs + br;
        f = f > 0.f ? f : 0.f;
        fout[(long)v * 32 + lane] = f;
        float a0 = bl, a1 = 0.f;
        #pragma unroll
        for (int c = 0; c < 16; c++) {
            a0 = fmaf(__shfl_sync(FULLM, f, 2 * c), wl[2 * c], a0);
            a1 = fmaf(__shfl_sync(FULLM, f, 2 * c + 1), wl[2 * c + 1], a1);
        }
        if (lane < 20) y[(long)v * 20 + lane] = a0 + a1;
    }
}

// ---------------- launcher ---------------------------------------------------
extern "C" void kernel_launch(void* const* d_in, const int* in_sizes, int n_in,
                              void* d_out, int out_size) {
    const float* feats      = (const float*)d_in[0];
    const int*   nbr_fine   = (const int*)  d_in[1];
    const int*   nbr_coarse = (const int*)  d_in[2];
    const int*   parent     = (const int*)  d_in[3];
    const int*   coff       = (const int*)  d_in[4];
    const float* W_sub      = (const float*)d_in[5];
    const float* W_e0       = (const float*)d_in[6];
    const float* g0         = (const float*)d_in[7];
    const float* b0         = (const float*)d_in[8];
    const float* W_down     = (const float*)d_in[9];
    const float* W_e1       = (const float*)d_in[10];
    const float* g1         = (const float*)d_in[11];
    const float* b1         = (const float*)d_in[12];
    const float* W_up       = (const float*)d_in[13];
    const float* W_dec      = (const float*)d_in[14];
    const float* g_outp     = (const float*)d_in[15];
    const float* b_outp     = (const float*)d_in[16];
    const float* W_lin      = (const float*)d_in[17];
    const float* b_lin      = (const float*)d_in[18];

    int N = in_sizes[0] / 3;
    int M = in_sizes[2] / 27;
    float inv_n = 1.0f / (float)N;
    float inv_m = 1.0f / (float)M;

    float* y    = (float*)d_out;
    float* fout = y + (long)N * 20;

    float *p_xv, *p_e0, *p_down, *p_e1, *p_up, *p_dec;
    int2 *p_pf, *p_pc; unsigned char *p_pfk, *p_pck; int *p_np;
    cudaGetSymbolAddress((void**)&p_xv,   g_xv);
    cudaGetSymbolAddress((void**)&p_e0,   g_e0);
    cudaGetSymbolAddress((void**)&p_down, g_down);
    cudaGetSymbolAddress((void**)&p_e1,   g_e1);
    cudaGetSymbolAddress((void**)&p_up,   g_up);
    cudaGetSymbolAddress((void**)&p_dec,  g_dec);
    cudaGetSymbolAddress((void**)&p_pf,   g_pf);
    cudaGetSymbolAddress((void**)&p_pc,   g_pc);
    cudaGetSymbolAddress((void**)&p_pfk,  g_pfk);
    cudaGetSymbolAddress((void**)&p_pck,  g_pck);
    cudaGetSymbolAddress((void**)&p_np,   g_np);

    cudaFuncSetAttribute(down_smem, cudaFuncAttributeMaxDynamicSharedMemorySize, 65536);
    cudaFuncSetAttribute(up_smem,   cudaFuncAttributeMaxDynamicSharedMemorySize, 65536);

    dim3 b256(256), b128(128);
    int GP = 1024;      // persistent grids (256 thr)
    int GH = 2048;      // conv64 kernels (128 thr)
    int GD = 444;       // 64KB-smem kernels

    pack_weights<<<(27 * 32 * 64 + 255) / 256, b256>>>(W_e0, W_e1, W_dec);
    zero_kernel<<<1024, b256>>>(M);

    // single-pass pair build (block-chunk reservation; k-major within chunk)
    int tilesF = (N + FILL_VPB - 1) / FILL_VPB;
    int tilesC = (M + FILL_VPB - 1) / FILL_VPB;
    fill_kernel<<<tilesF + tilesC, b256>>>(nbr_fine, N, tilesF, nbr_coarse, M);

    // encoder fine level
    conv3_center<<<GP, b256>>>(feats, W_sub, p_xv, N);
    conv3_pair  <<<GP, b256>>>(feats, W_sub, p_xv, p_pf, p_pfk, p_np + 0);
    conv32_center<<<GP, b256>>>(p_xv, W_e0, p_e0, N);
    conv32_pair  <<<GP, b256>>>(p_xv, p_e0, p_pf, p_pfk, p_np + 0);
    bn_stats<<<GP, b256>>>(p_e0, 0, 32, N);

    // down + coarse level (BN0 applied inline)
    down_smem<<<GD, b256, 65536>>>(p_e0, parent, coff, W_down, g0, b0, p_down, N, inv_n);
    conv64_center<<<GH, b128>>>(p_down, W_e1, p_e1, M);
    conv64_pair  <<<GH, b128>>>(p_down, p_e1, p_pc, p_pck, p_np + 1);
    bn_stats<<<GP, b256>>>(p_e1, 1, 64, M);

    // up + decoder (BN1 / BN0 applied inline)
    up_smem<<<GD, b256, 65536>>>(p_e1, parent, coff, W_up, g1, b1, p_up, N, inv_m);
    convcat_center<<<GP, b256>>>(p_e0, p_up, W_dec, g0, b0, p_dec, N, inv_n);
    convcat_pair  <<<GP, b256>>>(p_e0, p_up, g0, b0, p_dec, p_pf, p_pfk, p_np + 0, inv_n);
    bn_stats<<<GP, b256>>>(p_dec, 2, 32, N);

    // fused bnrelu + linear head, writes both outputs
    final_kernel<<<GP, b256>>>(p_dec, g_outp, b_outp, W_lin, b_lin, y, fout, N);
}